// round 1
// baseline (speedup 1.0000x reference)
#include <cuda_runtime.h>

#define L_FRAMES 16
#define C_CH     16
#define H_DIM    128
#define W_DIM    256
#define HW       (H_DIM * W_DIM)
#define DECAY_F  0.1f

// Channel-last scratch: [k][h][w][c], 16*128*256*16 floats = 32 MB
__device__ float g_imgT[L_FRAMES * HW * C_CH];

// ---------------------------------------------------------------------------
// Kernel 1: transpose img [k][c][h][w] -> g_imgT [k][h][w][c]
// grid: L*H blocks, W threads. Reads coalesced (fixed c, consecutive w),
// writes 64B contiguous per thread via 4x STG.128.
// ---------------------------------------------------------------------------
__global__ void transpose_kernel(const float* __restrict__ img) {
    const int kh = blockIdx.x;          // k*H + h
    const int w  = threadIdx.x;         // 0..255
    const int k  = kh >> 7;
    const int h  = kh & (H_DIM - 1);

    float v[C_CH];
#pragma unroll
    for (int c = 0; c < C_CH; c++) {
        v[c] = img[((k * C_CH + c) * H_DIM + h) * W_DIM + w];
    }

    float4* dst = reinterpret_cast<float4*>(&g_imgT[((size_t)kh * W_DIM + w) * C_CH]);
#pragma unroll
    for (int j = 0; j < 4; j++) {
        dst[j] = make_float4(v[4 * j + 0], v[4 * j + 1], v[4 * j + 2], v[4 * j + 3]);
    }
}

// ---------------------------------------------------------------------------
// Kernel 2: warped accumulation.
// blockIdx.y = target frame t, blockIdx.x covers 64 pixels * 4 channel-groups.
// Lane layout: cg = tid & 3, pixel = tid >> 2 -> 4 consecutive lanes load the
// 4 float4s (64B contiguous) of one bilinear tap.
// ---------------------------------------------------------------------------
__global__ void __launch_bounds__(256) sample_kernel(
    const float* __restrict__ cum_flow,   // [k][2][h][w]
    const float* __restrict__ mask,       // [t][k]
    const float* __restrict__ dist,       // [t][k]
    float* __restrict__ out)              // [t][c][h][w]
{
    const int t = blockIdx.y;

    __shared__ float ws[L_FRAMES];
    if (threadIdx.x < L_FRAMES) {
        int i = t * L_FRAMES + threadIdx.x;
        ws[threadIdx.x] = mask[i] * expf(-DECAY_F * dist[i]);
    }
    __syncthreads();

    const int tid = threadIdx.x;
    const int cg  = tid & 3;                          // channel group 0..3
    const int p   = blockIdx.x * 64 + (tid >> 2);     // pixel index 0..32767
    const int h   = p >> 8;                           // W = 256
    const int w   = p & (W_DIM - 1);

    const float base_x = (float)w * (2.0f / W_DIM) - 1.0f + (1.0f / W_DIM);
    const float base_y = (float)h * (2.0f / H_DIM) - 1.0f + (1.0f / H_DIM);

    const float ftx = cum_flow[(t * 2 + 0) * HW + p];
    const float fty = cum_flow[(t * 2 + 1) * HW + p];

    float acc0 = 0.0f, acc1 = 0.0f, acc2 = 0.0f, acc3 = 0.0f;

    const float4* __restrict__ src = reinterpret_cast<const float4*>(g_imgT);

#pragma unroll
    for (int k = 0; k < L_FRAMES; k++) {
        const float wk = ws[k];
        if (wk != 0.0f) {
            const float fkx = cum_flow[(k * 2 + 0) * HW + p];
            const float fky = cum_flow[(k * 2 + 1) * HW + p];

            // wrap gx into [0,2): a = mod(gx+1, 2)
            float a = (base_x + ftx - fkx) + 1.0f;
            a = a - 2.0f * floorf(a * 0.5f);
            const float gy = base_y + fty - fky;

            const float ix = a * (W_DIM * 0.5f) - 0.5f;
            const float iy = (gy + 1.0f) * (H_DIM * 0.5f) - 0.5f;

            const float x0f = floorf(ix);
            const float y0f = floorf(iy);
            const float wx = ix - x0f;
            const float wy = iy - y0f;

            const int x0 = (int)x0f;
            const int y0 = (int)y0f;
            // x wraps (power-of-two width: & works for negatives too)
            const int x0r = x0 & (W_DIM - 1);
            const int x1r = (x0 + 1) & (W_DIM - 1);
            // y clamps
            const int y0c = min(max(y0, 0), H_DIM - 1);
            const int y1c = min(max(y0 + 1, 0), H_DIM - 1);

            const int bk = k * HW;
            const float4 va = src[(size_t)(bk + y0c * W_DIM + x0r) * 4 + cg];
            const float4 vb = src[(size_t)(bk + y1c * W_DIM + x0r) * 4 + cg];
            const float4 vc = src[(size_t)(bk + y0c * W_DIM + x1r) * 4 + cg];
            const float4 vd = src[(size_t)(bk + y1c * W_DIM + x1r) * 4 + cg];

            const float w00 = wk * (1.0f - wx) * (1.0f - wy);
            const float w01 = wk * (1.0f - wx) * wy;
            const float w10 = wk * wx * (1.0f - wy);
            const float w11 = wk * wx * wy;

            acc0 += va.x * w00 + vb.x * w01 + vc.x * w10 + vd.x * w11;
            acc1 += va.y * w00 + vb.y * w01 + vc.y * w10 + vd.y * w11;
            acc2 += va.z * w00 + vb.z * w01 + vc.z * w10 + vd.z * w11;
            acc3 += va.w * w00 + vb.w * w01 + vc.w * w10 + vd.w * w11;
        }
    }

    const int cbase = (t * C_CH + cg * 4) * HW + p;
    out[cbase + 0 * HW] = acc0;
    out[cbase + 1 * HW] = acc1;
    out[cbase + 2 * HW] = acc2;
    out[cbase + 3 * HW] = acc3;
}

extern "C" void kernel_launch(void* const* d_in, const int* in_sizes, int n_in,
                              void* d_out, int out_size) {
    const float* img      = (const float*)d_in[0];  // (1,16,16,128,256)
    const float* cum_flow = (const float*)d_in[1];  // (1,16,2,128,256)
    const float* mask     = (const float*)d_in[2];  // (16,16)
    const float* dist     = (const float*)d_in[3];  // (16,16)
    float* out            = (float*)d_out;          // (1,16,16,128,256)

    transpose_kernel<<<L_FRAMES * H_DIM, W_DIM>>>(img);

    dim3 grid(HW / 64, L_FRAMES);   // 512 x 16 blocks
    sample_kernel<<<grid, 256>>>(cum_flow, mask, dist, out);
}

// round 2
// speedup vs baseline: 1.8350x; 1.8350x over previous
#include <cuda_runtime.h>
#include <cuda_fp16.h>

#define L_FRAMES 16
#define C_CH     16
#define H_DIM    128
#define W_DIM    256
#define HW       (H_DIM * W_DIM)
#define DECAY_F  0.1f

// Channel-last fp16 scratch: [k][h][w][c], 16*128*256*16 halves = 16 MB
__device__ __half g_imgT[L_FRAMES * HW * C_CH];

// ---------------------------------------------------------------------------
// Kernel 1: transpose + downconvert img [k][c][h][w] fp32 -> g_imgT [k][h][w][c] fp16
// grid: L*H blocks, W threads. Reads coalesced, each thread writes 32 B (2x STG.128).
// ---------------------------------------------------------------------------
__global__ void transpose_kernel(const float* __restrict__ img) {
    const int kh = blockIdx.x;          // k*H + h
    const int w  = threadIdx.x;         // 0..255
    const int k  = kh >> 7;
    const int h  = kh & (H_DIM - 1);

    __half2 v[8];
#pragma unroll
    for (int c = 0; c < 8; c++) {
        float a = img[((k * C_CH + 2 * c + 0) * H_DIM + h) * W_DIM + w];
        float b = img[((k * C_CH + 2 * c + 1) * H_DIM + h) * W_DIM + w];
        v[c] = __floats2half2_rn(a, b);
    }

    uint4* dst = reinterpret_cast<uint4*>(&g_imgT[((size_t)kh * W_DIM + w) * C_CH]);
    dst[0] = *reinterpret_cast<const uint4*>(&v[0]);
    dst[1] = *reinterpret_cast<const uint4*>(&v[4]);
}

// ---------------------------------------------------------------------------
// Kernel 2: warped accumulation.
// blockIdx.y = target frame t, blockIdx.x covers 64 pixels.
// Lane layout: 4 lanes per pixel: sub = tid&3, ch = sub&1 (channel half),
// xh = sub>>1 (x tap). Each lane loads 16 B (8 fp16 channels) per row per k.
// x-halves merged once after the k loop via shfl_xor(2).
// ---------------------------------------------------------------------------
__global__ void __launch_bounds__(256) sample_kernel(
    const float* __restrict__ cum_flow,   // [k][2][h][w]
    const float* __restrict__ mask,       // [t][k]
    const float* __restrict__ dist,       // [t][k]
    float* __restrict__ out)              // [t][c][h][w]
{
    const int t = blockIdx.y;

    __shared__ float ws[L_FRAMES];
    if (threadIdx.x < L_FRAMES) {
        int i = t * L_FRAMES + threadIdx.x;
        ws[threadIdx.x] = mask[i] * expf(-DECAY_F * dist[i]);
    }
    __syncthreads();

    const int tid = threadIdx.x;
    const int sub = tid & 3;
    const int ch  = sub & 1;        // channel half: channels [ch*8, ch*8+8)
    const int xh  = sub >> 1;       // x tap: 0 -> x0, 1 -> x0+1
    const int p   = blockIdx.x * 64 + (tid >> 2);   // pixel 0..32767
    const int h   = p >> 8;
    const int w   = p & (W_DIM - 1);

    const float base_x = (float)w * (2.0f / W_DIM) - 1.0f + (1.0f / W_DIM);
    const float base_y = (float)h * (2.0f / H_DIM) - 1.0f + (1.0f / H_DIM);

    const float ftx = cum_flow[(t * 2 + 0) * HW + p];
    const float fty = cum_flow[(t * 2 + 1) * HW + p];

    float acc[8];
#pragma unroll
    for (int j = 0; j < 8; j++) acc[j] = 0.0f;

    const __half* __restrict__ srcbase = g_imgT + ch * 8;

    for (int k = 0; k <= t; k++) {
        const float wk  = ws[k];
        const float fkx = cum_flow[(k * 2 + 0) * HW + p];
        const float fky = cum_flow[(k * 2 + 1) * HW + p];

        // wrap gx into [0,2): a = mod(gx+1, 2)
        float a = (base_x + ftx - fkx) + 1.0f;
        a = a - 2.0f * floorf(a * 0.5f);
        const float gy = base_y + fty - fky;

        const float ix = a * (W_DIM * 0.5f) - 0.5f;
        const float iy = (gy + 1.0f) * (H_DIM * 0.5f) - 0.5f;

        const float x0f = floorf(ix);
        const float y0f = floorf(iy);
        const float wx = ix - x0f;
        const float wy = iy - y0f;

        const int x0 = (int)x0f;
        const int y0 = (int)y0f;
        const int x   = (x0 + xh) & (W_DIM - 1);      // wrap (power-of-two)
        const int y0c = min(max(y0, 0), H_DIM - 1);   // clamp
        const int y1c = min(max(y0 + 1, 0), H_DIM - 1);

        const float xw = xh ? wx : (1.0f - wx);
        const float w0 = wk * xw * (1.0f - wy);
        const float w1 = wk * xw * wy;

        const int bk = k * HW;
        const uint4 u0 = *reinterpret_cast<const uint4*>(srcbase + (size_t)(bk + y0c * W_DIM + x) * C_CH);
        const uint4 u1 = *reinterpret_cast<const uint4*>(srcbase + (size_t)(bk + y1c * W_DIM + x) * C_CH);

        const __half2* h0 = reinterpret_cast<const __half2*>(&u0);
        const __half2* h1 = reinterpret_cast<const __half2*>(&u1);
#pragma unroll
        for (int j = 0; j < 4; j++) {
            float2 f0 = __half22float2(h0[j]);
            float2 f1 = __half22float2(h1[j]);
            acc[2 * j + 0] += f0.x * w0 + f1.x * w1;
            acc[2 * j + 1] += f0.y * w0 + f1.y * w1;
        }
    }

    // merge x-halves: partner lane differs in bit 1 of tid
#pragma unroll
    for (int j = 0; j < 8; j++)
        acc[j] += __shfl_xor_sync(0xffffffffu, acc[j], 2);

    // each lane writes 4 channels: [ch*8 + xh*4, +4)
    const int cbase = (t * C_CH + ch * 8 + xh * 4) * HW + p;
#pragma unroll
    for (int j = 0; j < 4; j++)
        out[cbase + j * HW] = acc[xh * 4 + j];
}

extern "C" void kernel_launch(void* const* d_in, const int* in_sizes, int n_in,
                              void* d_out, int out_size) {
    const float* img      = (const float*)d_in[0];  // (1,16,16,128,256)
    const float* cum_flow = (const float*)d_in[1];  // (1,16,2,128,256)
    const float* mask     = (const float*)d_in[2];  // (16,16)
    const float* dist     = (const float*)d_in[3];  // (16,16)
    float* out            = (float*)d_out;          // (1,16,16,128,256)

    transpose_kernel<<<L_FRAMES * H_DIM, W_DIM>>>(img);

    dim3 grid(HW / 64, L_FRAMES);   // 512 x 16 blocks
    sample_kernel<<<grid, 256>>>(cum_flow, mask, dist, out);
}

// round 3
// speedup vs baseline: 2.0428x; 1.1133x over previous
#include <cuda_runtime.h>
#include <cuda_fp16.h>

#define L_FRAMES 16
#define C_CH     16
#define H_DIM    128
#define W_DIM    256
#define HW       (H_DIM * W_DIM)
#define DECAY_F  0.1f

// Channel-last fp16 scratch: [k][h][w][c], 16 MB
__device__ __half  g_imgT[L_FRAMES * HW * C_CH];
// Interleaved flow: [k][h][w] float2, 4 MB
__device__ float2 g_flow2[L_FRAMES * HW];

// ---------------------------------------------------------------------------
// Prep: transpose img [k][c][h][w] fp32 -> [k][h][w][c] fp16, and pack flow
// [k][2][h][w] -> [k][h][w] float2. grid: L*H blocks, W threads.
// ---------------------------------------------------------------------------
__global__ void prep_kernel(const float* __restrict__ img,
                            const float* __restrict__ cum_flow) {
    const int kh = blockIdx.x;          // k*H + h
    const int w  = threadIdx.x;         // 0..255
    const int k  = kh >> 7;
    const int h  = kh & (H_DIM - 1);

    __half2 v[8];
#pragma unroll
    for (int c = 0; c < 8; c++) {
        float a = img[((k * C_CH + 2 * c + 0) * H_DIM + h) * W_DIM + w];
        float b = img[((k * C_CH + 2 * c + 1) * H_DIM + h) * W_DIM + w];
        v[c] = __floats2half2_rn(a, b);
    }
    uint4* dst = reinterpret_cast<uint4*>(&g_imgT[((size_t)kh * W_DIM + w) * C_CH]);
    dst[0] = *reinterpret_cast<const uint4*>(&v[0]);
    dst[1] = *reinterpret_cast<const uint4*>(&v[4]);

    const int p = (kh & (H_DIM - 1)) * W_DIM + w + 0; // h*W + w
    const float fx = cum_flow[(k * 2 + 0) * HW + p];
    const float fy = cum_flow[(k * 2 + 1) * HW + p];
    g_flow2[k * HW + p] = make_float2(fx, fy);
}

// ---------------------------------------------------------------------------
// Warped accumulation. blockIdx.y = t, blockIdx.x covers 64 pixels.
// 4 lanes per pixel: ch = tid&1 (channel half), xh = (tid>>1)&1 (x tap).
// Per k: 1 LDG.64 flow + 2 LDG.128 img + fp16 tap-combine + fp32 k-accum.
// ---------------------------------------------------------------------------
__global__ void __launch_bounds__(256) sample_kernel(
    const float* __restrict__ mask,       // [t][k]
    const float* __restrict__ dist,       // [t][k]
    float* __restrict__ out)              // [t][c][h][w]
{
    const int t = blockIdx.y;

    __shared__ float ws[L_FRAMES];
    if (threadIdx.x < L_FRAMES) {
        int i = t * L_FRAMES + threadIdx.x;
        ws[threadIdx.x] = mask[i] * expf(-DECAY_F * dist[i]);
    }
    __syncthreads();

    const int tid = threadIdx.x;
    const int sub = tid & 3;
    const int ch  = sub & 1;        // channel half: channels [ch*8, ch*8+8)
    const int xh  = sub >> 1;       // x tap: 0 -> x0, 1 -> x0+1
    const int p   = blockIdx.x * 64 + (tid >> 2);   // pixel 0..32767
    const int h   = p >> 8;
    const int w   = p & (W_DIM - 1);

    const float2 ft = g_flow2[t * HW + p];

    // Hoisted affine coords: ix = Ax - 128*fkx ; iy = Ay - 64*fky
    // base_x = w*(2/W) - 1 + 1/W ; ix = (base_x + ftx - fkx + 1)*(W/2) - 0.5
    const float base_x = (float)w * (2.0f / W_DIM) - 1.0f + (1.0f / W_DIM);
    const float base_y = (float)h * (2.0f / H_DIM) - 1.0f + (1.0f / H_DIM);
    const float Ax = (base_x + ft.x + 1.0f) * (W_DIM * 0.5f) - 0.5f;
    const float Ay = (base_y + ft.y + 1.0f) * (H_DIM * 0.5f) - 0.5f;

    // xw = xh ? wx : 1-wx  ->  xw = fma(sx, wx, cx)
    const float sx = xh ? 1.0f : -1.0f;
    const float cx = xh ? 0.0f : 1.0f;

    float acc[8];
#pragma unroll
    for (int j = 0; j < 8; j++) acc[j] = 0.0f;

    const __half* __restrict__ srcbase = g_imgT + ch * 8;
    const float2* __restrict__ flow = g_flow2 + p;

    for (int k = 0; k <= t; k++) {
        const float wk  = ws[k];
        const float2 fk = flow[k * HW];

        // unwrapped coords; integer wrap handles x periodicity exactly
        const float ix = fmaf(-(W_DIM * 0.5f), fk.x, Ax);
        const float iy = fmaf(-(H_DIM * 0.5f), fk.y, Ay);

        const int x0 = __float2int_rd(ix);
        const int y0 = __float2int_rd(iy);
        const float wx = ix - (float)x0;
        const float wy = iy - (float)y0;

        const int x   = (x0 + xh) & (W_DIM - 1);      // wrap
        const int y0c = min(max(y0, 0), H_DIM - 1);   // clamp
        const int y1c = min(max(y0 + 1, 0), H_DIM - 1);

        const float xw = fmaf(sx, wx, cx);
        const float tw = wk * xw;
        const float w1 = tw * wy;
        const float w0 = tw - w1;

        const __half2 w0h = __float2half2_rn(w0);
        const __half2 w1h = __float2half2_rn(w1);

        const int bk = k * HW;
        const uint4 u0 = *reinterpret_cast<const uint4*>(srcbase + (size_t)(bk + y0c * W_DIM + x) * C_CH);
        const uint4 u1 = *reinterpret_cast<const uint4*>(srcbase + (size_t)(bk + y1c * W_DIM + x) * C_CH);

        const __half2* h0 = reinterpret_cast<const __half2*>(&u0);
        const __half2* h1 = reinterpret_cast<const __half2*>(&u1);
#pragma unroll
        for (int j = 0; j < 4; j++) {
            __half2 s = __hmul2(h0[j], w0h);
            s = __hfma2(h1[j], w1h, s);
            float2 f = __half22float2(s);
            acc[2 * j + 0] += f.x;
            acc[2 * j + 1] += f.y;
        }
    }

    // merge x-halves: partner lane differs in bit 1 of tid
#pragma unroll
    for (int j = 0; j < 8; j++)
        acc[j] += __shfl_xor_sync(0xffffffffu, acc[j], 2);

    // each lane writes 4 channels: [ch*8 + xh*4, +4)
    const int cbase = (t * C_CH + ch * 8 + xh * 4) * HW + p;
#pragma unroll
    for (int j = 0; j < 4; j++)
        out[cbase + j * HW] = acc[xh * 4 + j];
}

extern "C" void kernel_launch(void* const* d_in, const int* in_sizes, int n_in,
                              void* d_out, int out_size) {
    const float* img      = (const float*)d_in[0];  // (1,16,16,128,256)
    const float* cum_flow = (const float*)d_in[1];  // (1,16,2,128,256)
    const float* mask     = (const float*)d_in[2];  // (16,16)
    const float* dist     = (const float*)d_in[3];  // (16,16)
    float* out            = (float*)d_out;          // (1,16,16,128,256)

    prep_kernel<<<L_FRAMES * H_DIM, W_DIM>>>(img, cum_flow);

    dim3 grid(HW / 64, L_FRAMES);   // 512 x 16 blocks
    sample_kernel<<<grid, 256>>>(mask, dist, out);
}